// round 14
// baseline (speedup 1.0000x reference)
#include <cuda_runtime.h>
#include <cuda_bf16.h>
#include <math.h>
#include <mma.h>

using namespace nvcuda;

#define S_SETS 48
#define M_ITEMS 128
#define DIN 128
#define DM 128
#define H_HEADS 4
#define DH 128
#define L_LAYERS 2
#define ROWS (S_SETS*M_ITEMS)   /* 6144 */
#define HD (H_HEADS*DH)         /* 512  */
#define QKVW 1536

#define PAs 36   /* gemm A-tile pitch (floats) */
#define PT 132   /* attn smem pitch (floats) */
#define PZ 136   /* gram pitch (bf16) */

// ---------------- device scratch ----------------
__device__ float g_mask[ROWS];
__device__ float g_x[ROWS*DIN];
__device__ float g_h[ROWS*DM];
__device__ float g_qkv[ROWS*QKVW];
__device__ float g_wproj[DIN*DM];
__device__ float g_wqkv[L_LAYERS*DM*QKVW];
__device__ float g_wh[L_LAYERS*HD*DM];
__device__ float g_wfc[L_LAYERS*DM*DM];
__device__ float g_wc[DM*HD];
__device__ float g_o[ROWS*HD];
__device__ float g_t[ROWS*DM];
__device__ __nv_bfloat16 g_z[ROWS*HD];
__device__ float g_B[S_SETS*S_SETS*H_HEADS];

__device__ __forceinline__ float gelu_f(float x){
    return 0.5f*x*(1.0f + erff(x*0.70710678118654752440f));
}
__device__ __forceinline__ float tf32r(float x){ return wmma::__float_to_tf32(x); }

__device__ __forceinline__ void cpa16(void* dst, const void* src){
    unsigned d = (unsigned)__cvta_generic_to_shared(dst);
    asm volatile("cp.async.cg.shared.global [%0], [%1], 16;\n" :: "r"(d), "l"(src));
}
__device__ __forceinline__ void cp_commit(){ asm volatile("cp.async.commit_group;\n"); }
template<int NG> __device__ __forceinline__ void cp_wait(){ asm volatile("cp.async.wait_group %0;\n" :: "n"(NG)); }

template<int NW>
__device__ __forceinline__ float block_reduce_sum(float v, float* red){
    int tid = threadIdx.x;
    #pragma unroll
    for (int o=16;o;o>>=1) v += __shfl_xor_sync(0xffffffffu, v, o);
    if ((tid&31)==0) red[tid>>5] = v;
    __syncthreads();
    if (tid < 32) {
        float r = (tid < NW) ? red[tid] : 0.0f;
        #pragma unroll
        for (int o=8;o;o>>=1) r += __shfl_xor_sync(0xffffffffu, r, o);
        if (tid==0) red[0] = r;
    }
    __syncthreads();
    float out = red[0];
    __syncthreads();
    return out;
}

// ---------------- item mask ----------------
__global__ void mask_kernel(const float* __restrict__ x, float* __restrict__ mask){
    int row = blockIdx.x*8 + (threadIdx.x>>5);
    int lane = threadIdx.x & 31;
    float4 v = reinterpret_cast<const float4*>(x + (long)row*DIN)[lane];
    bool nz = (v.x!=0.0f)||(v.y!=0.0f)||(v.z!=0.0f)||(v.w!=0.0f);
    unsigned b = __ballot_sync(0xffffffffu, nz);
    if (lane==0) mask[row] = b ? 1.0f : 0.0f;
}

// ---------------- fused prep: tf32-round x + all weights, pack qkv ----------------
__global__ void prep_kernel(
    const float* __restrict__ x, const float* __restrict__ wproj,
    const float* __restrict__ wh, const float* __restrict__ wfc, const float* __restrict__ wc,
    const float* __restrict__ Wq, const float* __restrict__ Wk, const float* __restrict__ Wv,
    float* __restrict__ ox, float* __restrict__ owproj, float* __restrict__ owh,
    float* __restrict__ owfc, float* __restrict__ owc, float* __restrict__ owqkv)
{
    int g = blockIdx.x*256 + threadIdx.x;
    if (g >= 356352) return;
    const float* src; float* dst;
    if (g < 196608){ src = x + (long)g*4; dst = ox + (long)g*4; }
    else if (g < 200704){ int o=g-196608; src=wproj+(long)o*4; dst=owproj+(long)o*4; }
    else if (g < 233472){ int o=g-200704; src=wh+(long)o*4;    dst=owh+(long)o*4; }
    else if (g < 241664){ int o=g-233472; src=wfc+(long)o*4;   dst=owfc+(long)o*4; }
    else if (g < 258048){ int o=g-241664; src=wc+(long)o*4;    dst=owc+(long)o*4; }
    else {
        int o = g-258048;
        int l = o / 49152, r2 = o % 49152;
        int r = r2 / 384, c4 = r2 % 384;
        int q = c4 >> 7, cq = c4 & 127;
        const float* s3 = (q==0)?Wq:(q==1)?Wk:Wv;
        src = s3 + (long)l*65536 + r*512 + cq*4;
        dst = owqkv + (long)l*196608 + r*1536 + q*512 + cq*4;
    }
    float4 v = *(const float4*)src;
    v.x=tf32r(v.x); v.y=tf32r(v.y); v.z=tf32r(v.z); v.w=tf32r(v.w);
    *(float4*)dst = v;
}

// ---------------- 3-stage cp.async WMMA-tf32 GEMM, templated BM x BN ----------------
// THREADS = BM*2. Warps tile (BM/32) x 2; warp tile 32 x (BN/2). K-chunk 32.
template<int BM, int BN>
__global__ __launch_bounds__(BM*2, 512/BM) void gemm_ca(
    const float* __restrict__ A, const float* __restrict__ B,
    float* __restrict__ C32, __nv_bfloat16* __restrict__ C16,
    int N, int K, int epi, const float* __restrict__ mask)
{
    constexpr int THREADS = BM*2;
    constexpr int PB_ = BN + 4;
    constexpr int PC_ = BN + 4;
    constexpr int F4R = BN/4;
    constexpr int NF  = BN/32;
    constexpr int BIT = 8*BN/THREADS;   // loadB iters
    extern __shared__ float sm[];
    float* Asb[3] = { sm, sm + BM*PAs, sm + 2*BM*PAs };
    float* Bsb[3] = { sm + 3*BM*PAs, sm + 3*BM*PAs + 32*PB_, sm + 3*BM*PAs + 2*32*PB_ };
    float* Cs = sm;
    int tid = threadIdx.x;
    int warp = tid >> 5;
    int wr = warp >> 1, wc = warp & 1;
    int row0 = blockIdx.y*BM, col0 = blockIdx.x*BN;

    wmma::fragment<wmma::accumulator, 16, 16, 8, float> acc[2][NF];
    #pragma unroll
    for (int i=0;i<2;i++)
        #pragma unroll
        for (int t=0;t<NF;t++) wmma::fill_fragment(acc[i][t], 0.0f);

    auto loadAB = [&](int buf, int k0){
        float* da = Asb[buf];
        #pragma unroll
        for (int t=0;t<4;t++){
            int idx = tid + t*THREADS;
            int m = idx>>3, kg = idx&7;
            cpa16(da + m*PAs + kg*4, A + (long)(row0+m)*K + k0 + kg*4);
        }
        float* db = Bsb[buf];
        #pragma unroll
        for (int t=0;t<BIT;t++){
            int idx = tid + t*THREADS;
            int kk = idx / F4R, ng = idx % F4R;
            cpa16(db + kk*PB_ + ng*4, B + (long)(k0+kk)*N + col0 + ng*4);
        }
        cp_commit();
    };

    int nch = K >> 5;
    loadAB(0, 0);
    if (nch > 1) loadAB(1, 32);

    int cur = 0;
    for (int c=0; c<nch; c++){
        if (c+1 < nch) cp_wait<1>(); else cp_wait<0>();
        __syncthreads();
        float* Asp = Asb[cur];
        float* Bsp = Bsb[cur];
        #pragma unroll
        for (int ks=0; ks<4; ks++){
            wmma::fragment<wmma::matrix_a, 16, 16, 8, wmma::precision::tf32, wmma::row_major> a0, a1;
            wmma::load_matrix_sync(a0, Asp + (wr*32    )*PAs + ks*8, PAs);
            wmma::load_matrix_sync(a1, Asp + (wr*32+16 )*PAs + ks*8, PAs);
            #pragma unroll
            for (int t=0;t<NF;t++){
                wmma::fragment<wmma::matrix_b, 16, 16, 8, wmma::precision::tf32, wmma::row_major> bf;
                wmma::load_matrix_sync(bf, Bsp + (ks*8)*PB_ + wc*(BN/2) + t*16, PB_);
                wmma::mma_sync(acc[0][t], a0, bf, acc[0][t]);
                wmma::mma_sync(acc[1][t], a1, bf, acc[1][t]);
            }
        }
        if (c+2 < nch){
            int nb = cur+2; if (nb >= 3) nb -= 3;
            loadAB(nb, (c+2)*32);
        }
        cur = (cur+1 == 3) ? 0 : cur+1;
    }
    __syncthreads();   // all MMAs done before Cs overlays buffers

    #pragma unroll
    for (int i=0;i<2;i++)
        #pragma unroll
        for (int t=0;t<NF;t++)
            wmma::store_matrix_sync(Cs + (wr*32+i*16)*PC_ + wc*(BN/2) + t*16, acc[i][t], PC_, wmma::mem_row_major);
    __syncthreads();
    #pragma unroll
    for (int t=0;t<BN/8;t++){
        int idx = tid + t*THREADS;
        int m = idx / F4R, ng = idx % F4R;
        int r = row0 + m;
        const float* p = Cs + m*PC_ + ng*4;
        float v0=p[0], v1=p[1], v2=p[2], v3=p[3];
        if (epi==1){
            float mrow = mask[r];
            v0 = gelu_f(v0)*mrow; v1 = gelu_f(v1)*mrow;
            v2 = gelu_f(v2)*mrow; v3 = gelu_f(v3)*mrow;
        }
        long off = (long)r*N + col0 + ng*4;
        if (C32){
            float4 outv;
            outv.x = tf32r(v0); outv.y = tf32r(v1); outv.z = tf32r(v2); outv.w = tf32r(v3);
            *(float4*)(C32 + off) = outv;
        }
        if (C16){
            __nv_bfloat162* d = (__nv_bfloat162*)(C16 + off);
            d[0] = __floats2bfloat162_rn(v0, v1);
            d[1] = __floats2bfloat162_rn(v2, v3);
        }
    }
}

// ---------------- attention per (head, set): WMMA-tf32 matmuls ----------------
__global__ __launch_bounds__(256) void attn_wmma(
    const float* __restrict__ qkv, float* __restrict__ o)
{
    int h = blockIdx.x, s = blockIdx.y;
    extern __shared__ float sm[];
    float* qs = sm;
    float* ks = sm + 128*PT;
    float* vs = sm + 2*128*PT;
    int tid = threadIdx.x;
    int warp = tid >> 5, lane = tid & 31;
    int wr = warp >> 1, wc = warp & 1;
    long base = (long)(s*M_ITEMS)*QKVW + h*DH;

    for (int idx=tid; idx<128*32; idx+=256){
        int m = idx>>5, dg = idx&31;
        const float* rowp = qkv + base + (long)m*QKVW + dg*4;
        *(float4*)(qs + m*PT + dg*4) = *(const float4*)(rowp);
        *(float4*)(ks + m*PT + dg*4) = *(const float4*)(rowp + 512);
        *(float4*)(vs + m*PT + dg*4) = *(const float4*)(rowp + 1024);
    }
    __syncthreads();

    const float scale = 0.08838834764831844f;  // 1/sqrt(128)

    {
        wmma::fragment<wmma::accumulator, 16, 16, 8, float> acc[2][4];
        #pragma unroll
        for (int i=0;i<2;i++)
            #pragma unroll
            for (int t=0;t<4;t++) wmma::fill_fragment(acc[i][t], 0.0f);
        #pragma unroll
        for (int k8=0; k8<16; k8++){
            wmma::fragment<wmma::matrix_a, 16, 16, 8, wmma::precision::tf32, wmma::row_major> a0, a1;
            wmma::load_matrix_sync(a0, qs + (wr*32    )*PT + k8*8, PT);
            wmma::load_matrix_sync(a1, qs + (wr*32+16 )*PT + k8*8, PT);
            #pragma unroll
            for (int t=0;t<4;t++){
                wmma::fragment<wmma::matrix_b, 16, 16, 8, wmma::precision::tf32, wmma::col_major> bf;
                wmma::load_matrix_sync(bf, ks + (wc*64 + t*16)*PT + k8*8, PT);
                wmma::mma_sync(acc[0][t], a0, bf, acc[0][t]);
                wmma::mma_sync(acc[1][t], a1, bf, acc[1][t]);
            }
        }
        __syncthreads();
        #pragma unroll
        for (int i=0;i<2;i++)
            #pragma unroll
            for (int t=0;t<4;t++){
                #pragma unroll
                for (int e=0;e<acc[i][t].num_elements;e++) acc[i][t].x[e] *= scale;
                wmma::store_matrix_sync(qs + (wr*32+i*16)*PT + wc*64 + t*16, acc[i][t], PT, wmma::mem_row_major);
            }
        __syncthreads();
    }

    for (int m=warp; m<128; m+=8){
        float* row = qs + m*PT;
        float vals[4]; float mx = -INFINITY;
        #pragma unroll
        for (int r=0;r<4;r++){ vals[r] = row[lane+32*r]; mx = fmaxf(mx, vals[r]); }
        #pragma unroll
        for (int off=16;off;off>>=1) mx = fmaxf(mx, __shfl_xor_sync(0xffffffffu, mx, off));
        float sum = 0.0f;
        #pragma unroll
        for (int r=0;r<4;r++){
            float e = (vals[r]!=0.0f) ? expf(vals[r]-mx) : 0.0f;
            vals[r] = e; sum += e;
        }
        #pragma unroll
        for (int off=16;off;off>>=1) sum += __shfl_xor_sync(0xffffffffu, sum, off);
        float inv = 1.0f/(sum + 1e-10f);
        #pragma unroll
        for (int r=0;r<4;r++) row[lane+32*r] = tf32r(vals[r]*inv);
    }
    __syncthreads();

    {
        long obase = (long)(s*M_ITEMS)*HD + h*DH;
        wmma::fragment<wmma::accumulator, 16, 16, 8, float> acc[2][4];
        #pragma unroll
        for (int i=0;i<2;i++)
            #pragma unroll
            for (int t=0;t<4;t++) wmma::fill_fragment(acc[i][t], 0.0f);
        #pragma unroll
        for (int k8=0; k8<16; k8++){
            wmma::fragment<wmma::matrix_a, 16, 16, 8, wmma::precision::tf32, wmma::row_major> a0, a1;
            wmma::load_matrix_sync(a0, qs + (wr*32    )*PT + k8*8, PT);
            wmma::load_matrix_sync(a1, qs + (wr*32+16 )*PT + k8*8, PT);
            #pragma unroll
            for (int t=0;t<4;t++){
                wmma::fragment<wmma::matrix_b, 16, 16, 8, wmma::precision::tf32, wmma::row_major> bf;
                wmma::load_matrix_sync(bf, vs + (k8*8)*PT + wc*64 + t*16, PT);
                wmma::mma_sync(acc[0][t], a0, bf, acc[0][t]);
                wmma::mma_sync(acc[1][t], a1, bf, acc[1][t]);
            }
        }
        #pragma unroll
        for (int i=0;i<2;i++)
            #pragma unroll
            for (int t=0;t<4;t++){
                #pragma unroll
                for (int e=0;e<acc[i][t].num_elements;e++) acc[i][t].x[e] = tf32r(acc[i][t].x[e]);
                wmma::store_matrix_sync(o + obase + (long)(wr*32+i*16)*HD + wc*64 + t*16, acc[i][t], HD, wmma::mem_row_major);
            }
    }
}

// ---------------- set_norm (512 threads), outputs tf32-rounded ----------------
__global__ __launch_bounds__(512) void setnorm_kernel(
    float* __restrict__ hbuf, const float* __restrict__ abuf,
    const float* __restrict__ mitem, const int* __restrict__ x_size,
    int apply_gelu)
{
    int s = blockIdx.x;
    extern __shared__ float sm[];
    float* ts = sm;              // [128][130]
    __shared__ float rs[128];
    __shared__ float red[32];
    int tid = threadIdx.x;
    long base = (long)s*M_ITEMS*DM;

    for (int idx=tid; idx<128*32; idx+=512){
        int m = idx>>5, dg = idx&31;
        float mrow = mitem[s*M_ITEMS+m];
        float4 hv = *(const float4*)(hbuf + base + (long)m*DM + dg*4);
        float4 av = *(const float4*)(abuf + base + (long)m*DM + dg*4);
        float a0 = apply_gelu ? gelu_f(av.x) : av.x;
        float a1 = apply_gelu ? gelu_f(av.y) : av.y;
        float a2 = apply_gelu ? gelu_f(av.z) : av.z;
        float a3 = apply_gelu ? gelu_f(av.w) : av.w;
        float* pt = ts + m*130 + dg*4;
        pt[0] = hv.x + a0*mrow; pt[1] = hv.y + a1*mrow;
        pt[2] = hv.z + a2*mrow; pt[3] = hv.w + a3*mrow;
    }
    __syncthreads();

    int warp = tid>>5, lane = tid&31;
    for (int m=warp; m<128; m+=16){
        float v = ts[m*130+lane] + ts[m*130+lane+32] + ts[m*130+lane+64] + ts[m*130+lane+96];
        #pragma unroll
        for (int off=16;off;off>>=1) v += __shfl_xor_sync(0xffffffffu, v, off);
        if (lane==0) rs[m] = v;
    }
    __syncthreads();

    float tv = (tid<128) ? rs[tid] : 0.0f;
    float total = block_reduce_sum<16>(tv, red);
    int szi = x_size[s]; if (szi < 1) szi = 1;
    float denom = (float)szi * 128.0f;
    float mean = total / denom;

    float vv = 0.0f;
    for (int idx=tid; idx<128*32; idx+=512){
        int m = idx>>5, dg = idx&31;
        if (rs[m] != 0.0f){
            float* pt = ts + m*130 + dg*4;
            float d0 = pt[0]-mean, d1 = pt[1]-mean, d2 = pt[2]-mean, d3 = pt[3]-mean;
            vv += d0*d0 + d1*d1 + d2*d2 + d3*d3;
        }
    }
    float vart = block_reduce_sum<16>(vv, red);
    float inv = 1.0f/(sqrtf(vart/denom) + 1e-8f);

    for (int idx=tid; idx<128*32; idx+=512){
        int m = idx>>5, dg = idx&31;
        float mr = (rs[m] != 0.0f) ? 1.0f : 0.0f;
        float* pt = ts + m*130 + dg*4;
        float4 outv;
        outv.x = tf32r((pt[0]-mean)*inv*mr);
        outv.y = tf32r((pt[1]-mean)*inv*mr);
        outv.z = tf32r((pt[2]-mean)*inv*mr);
        outv.w = tf32r((pt[3]-mean)*inv*mr);
        *(float4*)(hbuf + base + (long)m*DM + dg*4) = outv;
    }
}

// ---------------- paired cross-set Gram via bf16 WMMA ----------------
__global__ __launch_bounds__(256) void gram_pair_kernel(
    const __nv_bfloat16* __restrict__ z, float* __restrict__ Bout)
{
    int h = blockIdx.y;
    int p = blockIdx.x;
    int j = 0;
    while (p >= ((49-j)>>1)){ p -= (49-j)>>1; j++; }
    int i0 = j + 2*p;
    int i1 = i0 + 1;
    bool has1 = (i1 < S_SETS);
    int i1c = has1 ? i1 : i0;

    extern __shared__ char smraw[];
    __nv_bfloat16* zj = (__nv_bfloat16*)smraw;          // [128][PZ]
    __nv_bfloat16* zi = zj + 128*PZ;                    // [256][PZ]
    __shared__ float wsum[8];
    int tid = threadIdx.x;
    int warp = tid >> 5, lane = tid & 31;
    int wr = warp >> 2;
    int wc = warp & 3;
    long basej  = (long)(j  *M_ITEMS)*HD + h*DH;
    long basei0 = (long)(i0 *M_ITEMS)*HD + h*DH;
    long basei1 = (long)(i1c*M_ITEMS)*HD + h*DH;

    for (int idx=tid; idx<128*16; idx+=256){
        int m = idx>>4, g = idx&15;
        *(uint4*)(zj + m*PZ + g*8)        = *(const uint4*)(z + basej  + (long)m*HD + g*8);
        *(uint4*)(zi + m*PZ + g*8)        = *(const uint4*)(z + basei0 + (long)m*HD + g*8);
        *(uint4*)(zi + (128+m)*PZ + g*8)  = *(const uint4*)(z + basei1 + (long)m*HD + g*8);
    }
    __syncthreads();

    wmma::fragment<wmma::accumulator, 16, 16, 16, float> acc[4][4];
    #pragma unroll
    for (int a=0;a<4;a++)
        #pragma unroll
        for (int t=0;t<4;t++) wmma::fill_fragment(acc[a][t], 0.0f);

    #pragma unroll
    for (int ks=0; ks<8; ks++){
        wmma::fragment<wmma::matrix_a, 16, 16, 16, __nv_bfloat16, wmma::row_major> af[4];
        #pragma unroll
        for (int a=0;a<4;a++)
            wmma::load_matrix_sync(af[a], zj + (wr*64 + a*16)*PZ + ks*16, PZ);
        #pragma unroll
        for (int t=0;t<4;t++){
            wmma::fragment<wmma::matrix_b, 16, 16, 16, __nv_bfloat16, wmma::col_major> bfrag;
            wmma::load_matrix_sync(bfrag, zi + (wc*64 + t*16)*PZ + ks*16, PZ);
            #pragma unroll
            for (int a=0;a<4;a++)
                wmma::mma_sync(acc[a][t], af[a], bfrag, acc[a][t]);
        }
    }

    const float scale = 0.08838834764831844f;
    float lsum = 0.0f;
    #pragma unroll
    for (int a=0;a<4;a++)
        #pragma unroll
        for (int t=0;t<4;t++)
            #pragma unroll
            for (int e=0;e<acc[a][t].num_elements;e++){
                float vv = acc[a][t].x[e]*scale;
                lsum += (vv >= 0.0f) ? vv : 0.3f*vv;
            }
    #pragma unroll
    for (int o=16;o;o>>=1) lsum += __shfl_xor_sync(0xffffffffu, lsum, o);
    if (lane==0) wsum[warp] = lsum;
    __syncthreads();
    if (tid==0){
        float s0 = wsum[0]+wsum[1]+wsum[4]+wsum[5];
        float s1 = wsum[2]+wsum[3]+wsum[6]+wsum[7];
        Bout[(j*S_SETS+i0)*H_HEADS + h] = s0;
        Bout[(i0*S_SETS+j)*H_HEADS + h] = s0;
        if (has1){
            Bout[(j*S_SETS+i1)*H_HEADS + h] = s1;
            Bout[(i1*S_SETS+j)*H_HEADS + h] = s1;
        }
    }
}

// ---------------- finalize ----------------
__global__ void final_kernel(const float* __restrict__ Bm, const int* __restrict__ x_size,
                             const float* __restrict__ w2, float* __restrict__ out)
{
    int idx = blockIdx.x*256 + threadIdx.x;
    if (idx >= S_SETS*S_SETS) return;
    int j = idx / S_SETS, i = idx % S_SETS;
    int szi = x_size[i]; if (szi < 1) szi = 1;
    float acc = 0.0f;
    #pragma unroll
    for (int h=0; h<H_HEADS; h++) acc += Bm[(j*S_SETS+i)*H_HEADS + h] * w2[h];
    out[idx] = acc / (float)szi / (float)M_ITEMS;
}

// ---------------- launch ----------------
extern "C" void kernel_launch(void* const* d_in, const int* in_sizes, int n_in,
                              void* d_out, int out_size)
{
    const float* x      = (const float*)d_in[0];
    const int*   x_size = (const int*)  d_in[1];
    const float* W_proj = (const float*)d_in[2];
    const float* Wq     = (const float*)d_in[3];
    const float* Wk     = (const float*)d_in[4];
    const float* Wv     = (const float*)d_in[5];
    const float* Wh     = (const float*)d_in[6];
    const float* Wfc    = (const float*)d_in[7];
    const float* Wc     = (const float*)d_in[8];
    const float* w2     = (const float*)d_in[9];
    float* out = (float*)d_out;

    float *pm, *px, *ph, *pqkv, *pwproj, *pwqkv, *pwh, *pwfc, *pwc, *po, *pt, *pB;
    __nv_bfloat16 *pz;
    cudaGetSymbolAddress((void**)&pm, g_mask);
    cudaGetSymbolAddress((void**)&px, g_x);
    cudaGetSymbolAddress((void**)&ph, g_h);
    cudaGetSymbolAddress((void**)&pqkv, g_qkv);
    cudaGetSymbolAddress((void**)&pwproj, g_wproj);
    cudaGetSymbolAddress((void**)&pwqkv, g_wqkv);
    cudaGetSymbolAddress((void**)&pwh, g_wh);
    cudaGetSymbolAddress((void**)&pwfc, g_wfc);
    cudaGetSymbolAddress((void**)&pwc, g_wc);
    cudaGetSymbolAddress((void**)&po, g_o);
    cudaGetSymbolAddress((void**)&pt, g_t);
    cudaGetSymbolAddress((void**)&pz, g_z);
    cudaGetSymbolAddress((void**)&pB, g_B);

    const int GEMM6464_SMEM  = (3*64*PAs + 3*32*68)*4;    //  53760 B
    const int GEMM128_SMEM   = (3*128*PAs + 3*32*132)*4;  // 105984 B
    const int ATTN_SMEM      = 3*128*PT*4;                // 202752 B
    const int GRAM_SMEM      = 384*PZ*2;                  // 104448 B
    const int SN_SMEM        = 128*130*4;                 //  66560 B
    cudaFuncSetAttribute((void*)gemm_ca<64,64>,   cudaFuncAttributeMaxDynamicSharedMemorySize, GEMM6464_SMEM);
    cudaFuncSetAttribute((void*)gemm_ca<128,128>, cudaFuncAttributeMaxDynamicSharedMemorySize, GEMM128_SMEM);
    cudaFuncSetAttribute(attn_wmma,        cudaFuncAttributeMaxDynamicSharedMemorySize, ATTN_SMEM);
    cudaFuncSetAttribute(gram_pair_kernel, cudaFuncAttributeMaxDynamicSharedMemorySize, GRAM_SMEM);
    cudaFuncSetAttribute(setnorm_kernel,   cudaFuncAttributeMaxDynamicSharedMemorySize, SN_SMEM);

    mask_kernel<<<ROWS/8, 256>>>(x, pm);
    prep_kernel<<<1392, 256>>>(x, W_proj, Wh, Wfc, Wc, Wq, Wk, Wv,
                               px, pwproj, pwh, pwfc, pwc, pwqkv);

    gemm_ca<64,64><<<dim3(2, 96), 128, GEMM6464_SMEM>>>(px, pwproj, ph, nullptr, DM, DIN, 1, pm);

    for (int l=0; l<L_LAYERS; l++){
        gemm_ca<128,128><<<dim3(12, 48), 256, GEMM128_SMEM>>>(ph, pwqkv + (long)l*DM*QKVW, pqkv, nullptr, QKVW, DM, 0, nullptr);
        attn_wmma<<<dim3(H_HEADS, S_SETS), 256, ATTN_SMEM>>>(pqkv, po);
        gemm_ca<64,64><<<dim3(2, 96), 128, GEMM6464_SMEM>>>(po, pwh + (long)l*HD*DM, pt, nullptr, DM, HD, 0, nullptr);
        setnorm_kernel<<<S_SETS, 512, SN_SMEM>>>(ph, pt, pm, x_size, 0);
        gemm_ca<64,64><<<dim3(2, 96), 128, GEMM6464_SMEM>>>(ph, pwfc + (long)l*DM*DM, pt, nullptr, DM, DM, 0, nullptr);
        setnorm_kernel<<<S_SETS, 512, SN_SMEM>>>(ph, pt, pm, x_size, 1);
    }

    gemm_ca<128,128><<<dim3(4, 48), 256, GEMM128_SMEM>>>(ph, pwc, nullptr, pz, HD, DM, 0, nullptr);
    gram_pair_kernel<<<dim3(600, H_HEADS), 256, GRAM_SMEM>>>(pz, pB);
    final_kernel<<<(S_SETS*S_SETS + 255)/256, 256>>>(pB, x_size, w2, out);
}

// round 15
// speedup vs baseline: 1.6544x; 1.6544x over previous
#include <cuda_runtime.h>
#include <cuda_bf16.h>
#include <math.h>
#include <mma.h>

using namespace nvcuda;

#define S_SETS 48
#define M_ITEMS 128
#define DIN 128
#define DM 128
#define H_HEADS 4
#define DH 128
#define L_LAYERS 2
#define ROWS (S_SETS*M_ITEMS)   /* 6144 */
#define HD (H_HEADS*DH)         /* 512  */
#define QKVW 1536

#define PAs 36   /* gemm A-tile pitch (floats) */
#define PT 132   /* attn smem pitch (floats) */
#define PZ 136   /* gram pitch (bf16) */

// ---------------- device scratch ----------------
__device__ float g_mask[ROWS];
__device__ float g_x[ROWS*DIN];
__device__ float g_h[ROWS*DM];
__device__ float g_qkv[ROWS*QKVW];
__device__ float g_wproj[DIN*DM];
__device__ float g_wqkv[L_LAYERS*DM*QKVW];
__device__ float g_wh[L_LAYERS*HD*DM];
__device__ float g_wfc[L_LAYERS*DM*DM];
__device__ float g_wc[DM*HD];
__device__ float g_o[ROWS*HD];
__device__ float g_t[ROWS*DM];
__device__ __nv_bfloat16 g_z[ROWS*HD];
__device__ float g_B[S_SETS*S_SETS*H_HEADS];

__device__ __forceinline__ float gelu_f(float x){
    return 0.5f*x*(1.0f + erff(x*0.70710678118654752440f));
}
__device__ __forceinline__ float tf32r(float x){ return wmma::__float_to_tf32(x); }

__device__ __forceinline__ void cpa16(void* dst, const void* src){
    unsigned d = (unsigned)__cvta_generic_to_shared(dst);
    asm volatile("cp.async.cg.shared.global [%0], [%1], 16;\n" :: "r"(d), "l"(src));
}
__device__ __forceinline__ void cp_commit(){ asm volatile("cp.async.commit_group;\n"); }
template<int NG> __device__ __forceinline__ void cp_wait(){ asm volatile("cp.async.wait_group %0;\n" :: "n"(NG)); }

template<int NW>
__device__ __forceinline__ float block_reduce_sum(float v, float* red){
    int tid = threadIdx.x;
    #pragma unroll
    for (int o=16;o;o>>=1) v += __shfl_xor_sync(0xffffffffu, v, o);
    if ((tid&31)==0) red[tid>>5] = v;
    __syncthreads();
    if (tid < 32) {
        float r = (tid < NW) ? red[tid] : 0.0f;
        #pragma unroll
        for (int o=8;o;o>>=1) r += __shfl_xor_sync(0xffffffffu, r, o);
        if (tid==0) red[0] = r;
    }
    __syncthreads();
    float out = red[0];
    __syncthreads();
    return out;
}

// ---------------- item mask ----------------
__global__ void mask_kernel(const float* __restrict__ x, float* __restrict__ mask){
    int row = blockIdx.x*8 + (threadIdx.x>>5);
    int lane = threadIdx.x & 31;
    float4 v = reinterpret_cast<const float4*>(x + (long)row*DIN)[lane];
    bool nz = (v.x!=0.0f)||(v.y!=0.0f)||(v.z!=0.0f)||(v.w!=0.0f);
    unsigned b = __ballot_sync(0xffffffffu, nz);
    if (lane==0) mask[row] = b ? 1.0f : 0.0f;
}

// ---------------- fused prep: tf32-round x + all weights, pack qkv ----------------
__global__ void prep_kernel(
    const float* __restrict__ x, const float* __restrict__ wproj,
    const float* __restrict__ wh, const float* __restrict__ wfc, const float* __restrict__ wc,
    const float* __restrict__ Wq, const float* __restrict__ Wk, const float* __restrict__ Wv,
    float* __restrict__ ox, float* __restrict__ owproj, float* __restrict__ owh,
    float* __restrict__ owfc, float* __restrict__ owc, float* __restrict__ owqkv)
{
    int g = blockIdx.x*256 + threadIdx.x;
    if (g >= 356352) return;
    const float* src; float* dst;
    if (g < 196608){ src = x + (long)g*4; dst = ox + (long)g*4; }
    else if (g < 200704){ int o=g-196608; src=wproj+(long)o*4; dst=owproj+(long)o*4; }
    else if (g < 233472){ int o=g-200704; src=wh+(long)o*4;    dst=owh+(long)o*4; }
    else if (g < 241664){ int o=g-233472; src=wfc+(long)o*4;   dst=owfc+(long)o*4; }
    else if (g < 258048){ int o=g-241664; src=wc+(long)o*4;    dst=owc+(long)o*4; }
    else {
        int o = g-258048;
        int l = o / 49152, r2 = o % 49152;
        int r = r2 / 384, c4 = r2 % 384;
        int q = c4 >> 7, cq = c4 & 127;
        const float* s3 = (q==0)?Wq:(q==1)?Wk:Wv;
        src = s3 + (long)l*65536 + r*512 + cq*4;
        dst = owqkv + (long)l*196608 + r*1536 + q*512 + cq*4;
    }
    float4 v = *(const float4*)src;
    v.x=tf32r(v.x); v.y=tf32r(v.y); v.z=tf32r(v.z); v.w=tf32r(v.w);
    *(float4*)dst = v;
}

// ---------------- 3-stage cp.async WMMA-tf32 GEMM, templated BM x BN ----------------
// THREADS = BM*2. Warps tile (BM/32) x 2; warp tile 32 x (BN/2). K-chunk 32.
// min-blocks: BM=64 -> 4 CTAs (128 regs/thr avail), BM=128 -> 2 CTAs (128 regs/thr).
template<int BM, int BN>
__global__ __launch_bounds__(BM*2, (BM==64 ? 4 : 2)) void gemm_ca(
    const float* __restrict__ A, const float* __restrict__ B,
    float* __restrict__ C32, __nv_bfloat16* __restrict__ C16,
    int N, int K, int epi, const float* __restrict__ mask)
{
    constexpr int THREADS = BM*2;
    constexpr int PB_ = BN + 4;
    constexpr int PC_ = BN + 4;
    constexpr int F4R = BN/4;
    constexpr int NF  = BN/32;
    constexpr int BIT = 8*BN/THREADS;   // loadB iters
    extern __shared__ float sm[];
    float* Asb[3] = { sm, sm + BM*PAs, sm + 2*BM*PAs };
    float* Bsb[3] = { sm + 3*BM*PAs, sm + 3*BM*PAs + 32*PB_, sm + 3*BM*PAs + 2*32*PB_ };
    float* Cs = sm;
    int tid = threadIdx.x;
    int warp = tid >> 5;
    int wr = warp >> 1, wc = warp & 1;
    int row0 = blockIdx.y*BM, col0 = blockIdx.x*BN;

    wmma::fragment<wmma::accumulator, 16, 16, 8, float> acc[2][NF];
    #pragma unroll
    for (int i=0;i<2;i++)
        #pragma unroll
        for (int t=0;t<NF;t++) wmma::fill_fragment(acc[i][t], 0.0f);

    auto loadAB = [&](int buf, int k0){
        float* da = Asb[buf];
        #pragma unroll
        for (int t=0;t<4;t++){
            int idx = tid + t*THREADS;
            int m = idx>>3, kg = idx&7;
            cpa16(da + m*PAs + kg*4, A + (long)(row0+m)*K + k0 + kg*4);
        }
        float* db = Bsb[buf];
        #pragma unroll
        for (int t=0;t<BIT;t++){
            int idx = tid + t*THREADS;
            int kk = idx / F4R, ng = idx % F4R;
            cpa16(db + kk*PB_ + ng*4, B + (long)(k0+kk)*N + col0 + ng*4);
        }
        cp_commit();
    };

    int nch = K >> 5;
    loadAB(0, 0);
    if (nch > 1) loadAB(1, 32);

    int cur = 0;
    for (int c=0; c<nch; c++){
        if (c+1 < nch) cp_wait<1>(); else cp_wait<0>();
        __syncthreads();
        float* Asp = Asb[cur];
        float* Bsp = Bsb[cur];
        #pragma unroll
        for (int ks=0; ks<4; ks++){
            wmma::fragment<wmma::matrix_a, 16, 16, 8, wmma::precision::tf32, wmma::row_major> a0, a1;
            wmma::load_matrix_sync(a0, Asp + (wr*32    )*PAs + ks*8, PAs);
            wmma::load_matrix_sync(a1, Asp + (wr*32+16 )*PAs + ks*8, PAs);
            #pragma unroll
            for (int t=0;t<NF;t++){
                wmma::fragment<wmma::matrix_b, 16, 16, 8, wmma::precision::tf32, wmma::row_major> bf;
                wmma::load_matrix_sync(bf, Bsp + (ks*8)*PB_ + wc*(BN/2) + t*16, PB_);
                wmma::mma_sync(acc[0][t], a0, bf, acc[0][t]);
                wmma::mma_sync(acc[1][t], a1, bf, acc[1][t]);
            }
        }
        if (c+2 < nch){
            int nb = cur+2; if (nb >= 3) nb -= 3;
            loadAB(nb, (c+2)*32);
        }
        cur = (cur+1 == 3) ? 0 : cur+1;
    }
    __syncthreads();   // all MMAs done before Cs overlays buffers

    #pragma unroll
    for (int i=0;i<2;i++)
        #pragma unroll
        for (int t=0;t<NF;t++)
            wmma::store_matrix_sync(Cs + (wr*32+i*16)*PC_ + wc*(BN/2) + t*16, acc[i][t], PC_, wmma::mem_row_major);
    __syncthreads();
    #pragma unroll
    for (int t=0;t<BN/8;t++){
        int idx = tid + t*THREADS;
        int m = idx / F4R, ng = idx % F4R;
        int r = row0 + m;
        const float* p = Cs + m*PC_ + ng*4;
        float v0=p[0], v1=p[1], v2=p[2], v3=p[3];
        if (epi==1){
            float mrow = mask[r];
            v0 = gelu_f(v0)*mrow; v1 = gelu_f(v1)*mrow;
            v2 = gelu_f(v2)*mrow; v3 = gelu_f(v3)*mrow;
        }
        long off = (long)r*N + col0 + ng*4;
        if (C32){
            float4 outv;
            outv.x = tf32r(v0); outv.y = tf32r(v1); outv.z = tf32r(v2); outv.w = tf32r(v3);
            *(float4*)(C32 + off) = outv;
        }
        if (C16){
            __nv_bfloat162* d = (__nv_bfloat162*)(C16 + off);
            d[0] = __floats2bfloat162_rn(v0, v1);
            d[1] = __floats2bfloat162_rn(v2, v3);
        }
    }
}

// ---------------- attention per (head, set): WMMA-tf32 matmuls ----------------
__global__ __launch_bounds__(256) void attn_wmma(
    const float* __restrict__ qkv, float* __restrict__ o)
{
    int h = blockIdx.x, s = blockIdx.y;
    extern __shared__ float sm[];
    float* qs = sm;
    float* ks = sm + 128*PT;
    float* vs = sm + 2*128*PT;
    int tid = threadIdx.x;
    int warp = tid >> 5, lane = tid & 31;
    int wr = warp >> 1, wc = warp & 1;
    long base = (long)(s*M_ITEMS)*QKVW + h*DH;

    for (int idx=tid; idx<128*32; idx+=256){
        int m = idx>>5, dg = idx&31;
        const float* rowp = qkv + base + (long)m*QKVW + dg*4;
        *(float4*)(qs + m*PT + dg*4) = *(const float4*)(rowp);
        *(float4*)(ks + m*PT + dg*4) = *(const float4*)(rowp + 512);
        *(float4*)(vs + m*PT + dg*4) = *(const float4*)(rowp + 1024);
    }
    __syncthreads();

    const float scale = 0.08838834764831844f;  // 1/sqrt(128)

    {
        wmma::fragment<wmma::accumulator, 16, 16, 8, float> acc[2][4];
        #pragma unroll
        for (int i=0;i<2;i++)
            #pragma unroll
            for (int t=0;t<4;t++) wmma::fill_fragment(acc[i][t], 0.0f);
        #pragma unroll
        for (int k8=0; k8<16; k8++){
            wmma::fragment<wmma::matrix_a, 16, 16, 8, wmma::precision::tf32, wmma::row_major> a0, a1;
            wmma::load_matrix_sync(a0, qs + (wr*32    )*PT + k8*8, PT);
            wmma::load_matrix_sync(a1, qs + (wr*32+16 )*PT + k8*8, PT);
            #pragma unroll
            for (int t=0;t<4;t++){
                wmma::fragment<wmma::matrix_b, 16, 16, 8, wmma::precision::tf32, wmma::col_major> bf;
                wmma::load_matrix_sync(bf, ks + (wc*64 + t*16)*PT + k8*8, PT);
                wmma::mma_sync(acc[0][t], a0, bf, acc[0][t]);
                wmma::mma_sync(acc[1][t], a1, bf, acc[1][t]);
            }
        }
        __syncthreads();
        #pragma unroll
        for (int i=0;i<2;i++)
            #pragma unroll
            for (int t=0;t<4;t++){
                #pragma unroll
                for (int e=0;e<acc[i][t].num_elements;e++) acc[i][t].x[e] *= scale;
                wmma::store_matrix_sync(qs + (wr*32+i*16)*PT + wc*64 + t*16, acc[i][t], PT, wmma::mem_row_major);
            }
        __syncthreads();
    }

    for (int m=warp; m<128; m+=8){
        float* row = qs + m*PT;
        float vals[4]; float mx = -INFINITY;
        #pragma unroll
        for (int r=0;r<4;r++){ vals[r] = row[lane+32*r]; mx = fmaxf(mx, vals[r]); }
        #pragma unroll
        for (int off=16;off;off>>=1) mx = fmaxf(mx, __shfl_xor_sync(0xffffffffu, mx, off));
        float sum = 0.0f;
        #pragma unroll
        for (int r=0;r<4;r++){
            float e = (vals[r]!=0.0f) ? expf(vals[r]-mx) : 0.0f;
            vals[r] = e; sum += e;
        }
        #pragma unroll
        for (int off=16;off;off>>=1) sum += __shfl_xor_sync(0xffffffffu, sum, off);
        float inv = 1.0f/(sum + 1e-10f);
        #pragma unroll
        for (int r=0;r<4;r++) row[lane+32*r] = tf32r(vals[r]*inv);
    }
    __syncthreads();

    {
        long obase = (long)(s*M_ITEMS)*HD + h*DH;
        wmma::fragment<wmma::accumulator, 16, 16, 8, float> acc[2][4];
        #pragma unroll
        for (int i=0;i<2;i++)
            #pragma unroll
            for (int t=0;t<4;t++) wmma::fill_fragment(acc[i][t], 0.0f);
        #pragma unroll
        for (int k8=0; k8<16; k8++){
            wmma::fragment<wmma::matrix_a, 16, 16, 8, wmma::precision::tf32, wmma::row_major> a0, a1;
            wmma::load_matrix_sync(a0, qs + (wr*32    )*PT + k8*8, PT);
            wmma::load_matrix_sync(a1, qs + (wr*32+16 )*PT + k8*8, PT);
            #pragma unroll
            for (int t=0;t<4;t++){
                wmma::fragment<wmma::matrix_b, 16, 16, 8, wmma::precision::tf32, wmma::row_major> bf;
                wmma::load_matrix_sync(bf, vs + (k8*8)*PT + wc*64 + t*16, PT);
                wmma::mma_sync(acc[0][t], a0, bf, acc[0][t]);
                wmma::mma_sync(acc[1][t], a1, bf, acc[1][t]);
            }
        }
        #pragma unroll
        for (int i=0;i<2;i++)
            #pragma unroll
            for (int t=0;t<4;t++){
                #pragma unroll
                for (int e=0;e<acc[i][t].num_elements;e++) acc[i][t].x[e] = tf32r(acc[i][t].x[e]);
                wmma::store_matrix_sync(o + obase + (long)(wr*32+i*16)*HD + wc*64 + t*16, acc[i][t], HD, wmma::mem_row_major);
            }
    }
}

// ---------------- set_norm (512 threads), outputs tf32-rounded ----------------
__global__ __launch_bounds__(512) void setnorm_kernel(
    float* __restrict__ hbuf, const float* __restrict__ abuf,
    const float* __restrict__ mitem, const int* __restrict__ x_size,
    int apply_gelu)
{
    int s = blockIdx.x;
    extern __shared__ float sm[];
    float* ts = sm;              // [128][130]
    __shared__ float rs[128];
    __shared__ float red[32];
    int tid = threadIdx.x;
    long base = (long)s*M_ITEMS*DM;

    for (int idx=tid; idx<128*32; idx+=512){
        int m = idx>>5, dg = idx&31;
        float mrow = mitem[s*M_ITEMS+m];
        float4 hv = *(const float4*)(hbuf + base + (long)m*DM + dg*4);
        float4 av = *(const float4*)(abuf + base + (long)m*DM + dg*4);
        float a0 = apply_gelu ? gelu_f(av.x) : av.x;
        float a1 = apply_gelu ? gelu_f(av.y) : av.y;
        float a2 = apply_gelu ? gelu_f(av.z) : av.z;
        float a3 = apply_gelu ? gelu_f(av.w) : av.w;
        float* pt = ts + m*130 + dg*4;
        pt[0] = hv.x + a0*mrow; pt[1] = hv.y + a1*mrow;
        pt[2] = hv.z + a2*mrow; pt[3] = hv.w + a3*mrow;
    }
    __syncthreads();

    int warp = tid>>5, lane = tid&31;
    for (int m=warp; m<128; m+=16){
        float v = ts[m*130+lane] + ts[m*130+lane+32] + ts[m*130+lane+64] + ts[m*130+lane+96];
        #pragma unroll
        for (int off=16;off;off>>=1) v += __shfl_xor_sync(0xffffffffu, v, off);
        if (lane==0) rs[m] = v;
    }
    __syncthreads();

    float tv = (tid<128) ? rs[tid] : 0.0f;
    float total = block_reduce_sum<16>(tv, red);
    int szi = x_size[s]; if (szi < 1) szi = 1;
    float denom = (float)szi * 128.0f;
    float mean = total / denom;

    float vv = 0.0f;
    for (int idx=tid; idx<128*32; idx+=512){
        int m = idx>>5, dg = idx&31;
        if (rs[m] != 0.0f){
            float* pt = ts + m*130 + dg*4;
            float d0 = pt[0]-mean, d1 = pt[1]-mean, d2 = pt[2]-mean, d3 = pt[3]-mean;
            vv += d0*d0 + d1*d1 + d2*d2 + d3*d3;
        }
    }
    float vart = block_reduce_sum<16>(vv, red);
    float inv = 1.0f/(sqrtf(vart/denom) + 1e-8f);

    for (int idx=tid; idx<128*32; idx+=512){
        int m = idx>>5, dg = idx&31;
        float mr = (rs[m] != 0.0f) ? 1.0f : 0.0f;
        float* pt = ts + m*130 + dg*4;
        float4 outv;
        outv.x = tf32r((pt[0]-mean)*inv*mr);
        outv.y = tf32r((pt[1]-mean)*inv*mr);
        outv.z = tf32r((pt[2]-mean)*inv*mr);
        outv.w = tf32r((pt[3]-mean)*inv*mr);
        *(float4*)(hbuf + base + (long)m*DM + dg*4) = outv;
    }
}

// ---------------- paired cross-set Gram via bf16 WMMA ----------------
__global__ __launch_bounds__(256) void gram_pair_kernel(
    const __nv_bfloat16* __restrict__ z, float* __restrict__ Bout)
{
    int h = blockIdx.y;
    int p = blockIdx.x;
    int j = 0;
    while (p >= ((49-j)>>1)){ p -= (49-j)>>1; j++; }
    int i0 = j + 2*p;
    int i1 = i0 + 1;
    bool has1 = (i1 < S_SETS);
    int i1c = has1 ? i1 : i0;

    extern __shared__ char smraw[];
    __nv_bfloat16* zj = (__nv_bfloat16*)smraw;          // [128][PZ]
    __nv_bfloat16* zi = zj + 128*PZ;                    // [256][PZ]
    __shared__ float wsum[8];
    int tid = threadIdx.x;
    int warp = tid >> 5, lane = tid & 31;
    int wr = warp >> 2;
    int wc = warp & 3;
    long basej  = (long)(j  *M_ITEMS)*HD + h*DH;
    long basei0 = (long)(i0 *M_ITEMS)*HD + h*DH;
    long basei1 = (long)(i1c*M_ITEMS)*HD + h*DH;

    for (int idx=tid; idx<128*16; idx+=256){
        int m = idx>>4, g = idx&15;
        *(uint4*)(zj + m*PZ + g*8)        = *(const uint4*)(z + basej  + (long)m*HD + g*8);
        *(uint4*)(zi + m*PZ + g*8)        = *(const uint4*)(z + basei0 + (long)m*HD + g*8);
        *(uint4*)(zi + (128+m)*PZ + g*8)  = *(const uint4*)(z + basei1 + (long)m*HD + g*8);
    }
    __syncthreads();

    wmma::fragment<wmma::accumulator, 16, 16, 16, float> acc[4][4];
    #pragma unroll
    for (int a=0;a<4;a++)
        #pragma unroll
        for (int t=0;t<4;t++) wmma::fill_fragment(acc[a][t], 0.0f);

    #pragma unroll
    for (int ks=0; ks<8; ks++){
        wmma::fragment<wmma::matrix_a, 16, 16, 16, __nv_bfloat16, wmma::row_major> af[4];
        #pragma unroll
        for (int a=0;a<4;a++)
            wmma::load_matrix_sync(af[a], zj + (wr*64 + a*16)*PZ + ks*16, PZ);
        #pragma unroll
        for (int t=0;t<4;t++){
            wmma::fragment<wmma::matrix_b, 16, 16, 16, __nv_bfloat16, wmma::col_major> bfrag;
            wmma::load_matrix_sync(bfrag, zi + (wc*64 + t*16)*PZ + ks*16, PZ);
            #pragma unroll
            for (int a=0;a<4;a++)
                wmma::mma_sync(acc[a][t], af[a], bfrag, acc[a][t]);
        }
    }

    const float scale = 0.08838834764831844f;
    float lsum = 0.0f;
    #pragma unroll
    for (int a=0;a<4;a++)
        #pragma unroll
        for (int t=0;t<4;t++)
            #pragma unroll
            for (int e=0;e<acc[a][t].num_elements;e++){
                float vv = acc[a][t].x[e]*scale;
                lsum += (vv >= 0.0f) ? vv : 0.3f*vv;
            }
    #pragma unroll
    for (int o=16;o;o>>=1) lsum += __shfl_xor_sync(0xffffffffu, lsum, o);
    if (lane==0) wsum[warp] = lsum;
    __syncthreads();
    if (tid==0){
        float s0 = wsum[0]+wsum[1]+wsum[4]+wsum[5];
        float s1 = wsum[2]+wsum[3]+wsum[6]+wsum[7];
        Bout[(j*S_SETS+i0)*H_HEADS + h] = s0;
        Bout[(i0*S_SETS+j)*H_HEADS + h] = s0;
        if (has1){
            Bout[(j*S_SETS+i1)*H_HEADS + h] = s1;
            Bout[(i1*S_SETS+j)*H_HEADS + h] = s1;
        }
    }
}

// ---------------- finalize ----------------
__global__ void final_kernel(const float* __restrict__ Bm, const int* __restrict__ x_size,
                             const float* __restrict__ w2, float* __restrict__ out)
{
    int idx = blockIdx.x*256 + threadIdx.x;
    if (idx >= S_SETS*S_SETS) return;
    int j = idx / S_SETS, i = idx % S_SETS;
    int szi = x_size[i]; if (szi < 1) szi = 1;
    float acc = 0.0f;
    #pragma unroll
    for (int h=0; h<H_HEADS; h++) acc += Bm[(j*S_SETS+i)*H_HEADS + h] * w2[h];
    out[idx] = acc / (float)szi / (float)M_ITEMS;
}

// ---------------- launch ----------------
extern "C" void kernel_launch(void* const* d_in, const int* in_sizes, int n_in,
                              void* d_out, int out_size)
{
    const float* x      = (const float*)d_in[0];
    const int*   x_size = (const int*)  d_in[1];
    const float* W_proj = (const float*)d_in[2];
    const float* Wq     = (const float*)d_in[3];
    const float* Wk     = (const float*)d_in[4];
    const float* Wv     = (const float*)d_in[5];
    const float* Wh     = (const float*)d_in[6];
    const float* Wfc    = (const float*)d_in[7];
    const float* Wc     = (const float*)d_in[8];
    const float* w2     = (const float*)d_in[9];
    float* out = (float*)d_out;

    float *pm, *px, *ph, *pqkv, *pwproj, *pwqkv, *pwh, *pwfc, *pwc, *po, *pt, *pB;
    __nv_bfloat16 *pz;
    cudaGetSymbolAddress((void**)&pm, g_mask);
    cudaGetSymbolAddress((void**)&px, g_x);
    cudaGetSymbolAddress((void**)&ph, g_h);
    cudaGetSymbolAddress((void**)&pqkv, g_qkv);
    cudaGetSymbolAddress((void**)&pwproj, g_wproj);
    cudaGetSymbolAddress((void**)&pwqkv, g_wqkv);
    cudaGetSymbolAddress((void**)&pwh, g_wh);
    cudaGetSymbolAddress((void**)&pwfc, g_wfc);
    cudaGetSymbolAddress((void**)&pwc, g_wc);
    cudaGetSymbolAddress((void**)&po, g_o);
    cudaGetSymbolAddress((void**)&pt, g_t);
    cudaGetSymbolAddress((void**)&pz, g_z);
    cudaGetSymbolAddress((void**)&pB, g_B);

    const int GEMM6464_SMEM  = (3*64*PAs + 3*32*68)*4;    //  53760 B
    const int GEMM128_SMEM   = (3*128*PAs + 3*32*132)*4;  // 105984 B
    const int ATTN_SMEM      = 3*128*PT*4;                // 202752 B
    const int GRAM_SMEM      = 384*PZ*2;                  // 104448 B
    const int SN_SMEM        = 128*130*4;                 //  66560 B
    cudaFuncSetAttribute((void*)gemm_ca<64,64>,   cudaFuncAttributeMaxDynamicSharedMemorySize, GEMM6464_SMEM);
    cudaFuncSetAttribute((void*)gemm_ca<128,128>, cudaFuncAttributeMaxDynamicSharedMemorySize, GEMM128_SMEM);
    cudaFuncSetAttribute(attn_wmma,        cudaFuncAttributeMaxDynamicSharedMemorySize, ATTN_SMEM);
    cudaFuncSetAttribute(gram_pair_kernel, cudaFuncAttributeMaxDynamicSharedMemorySize, GRAM_SMEM);
    cudaFuncSetAttribute(setnorm_kernel,   cudaFuncAttributeMaxDynamicSharedMemorySize, SN_SMEM);

    mask_kernel<<<ROWS/8, 256>>>(x, pm);
    prep_kernel<<<1392, 256>>>(x, W_proj, Wh, Wfc, Wc, Wq, Wk, Wv,
                               px, pwproj, pwh, pwfc, pwc, pwqkv);

    gemm_ca<64,64><<<dim3(2, 96), 128, GEMM6464_SMEM>>>(px, pwproj, ph, nullptr, DM, DIN, 1, pm);

    for (int l=0; l<L_LAYERS; l++){
        gemm_ca<128,128><<<dim3(12, 48), 256, GEMM128_SMEM>>>(ph, pwqkv + (long)l*DM*QKVW, pqkv, nullptr, QKVW, DM, 0, nullptr);
        attn_wmma<<<dim3(H_HEADS, S_SETS), 256, ATTN_SMEM>>>(pqkv, po);
        gemm_ca<64,64><<<dim3(2, 96), 128, GEMM6464_SMEM>>>(po, pwh + (long)l*HD*DM, pt, nullptr, DM, HD, 0, nullptr);
        setnorm_kernel<<<S_SETS, 512, SN_SMEM>>>(ph, pt, pm, x_size, 0);
        gemm_ca<64,64><<<dim3(2, 96), 128, GEMM6464_SMEM>>>(ph, pwfc + (long)l*DM*DM, pt, nullptr, DM, DM, 0, nullptr);
        setnorm_kernel<<<S_SETS, 512, SN_SMEM>>>(ph, pt, pm, x_size, 1);
    }

    gemm_ca<128,128><<<dim3(4, 48), 256, GEMM128_SMEM>>>(ph, pwc, nullptr, pz, HD, DM, 0, nullptr);
    gram_pair_kernel<<<dim3(600, H_HEADS), 256, GRAM_SMEM>>>(pz, pB);
    final_kernel<<<(S_SETS*S_SETS + 255)/256, 256>>>(pB, x_size, w2, out);
}